// round 2
// baseline (speedup 1.0000x reference)
#include <cuda_runtime.h>
#include <cstdint>

#define BINS 10
#define C 16

// Global scratch (allocation-free): per-bin nll sums (double) and counts.
__device__ double             g_bin_nll[BINS];
__device__ unsigned long long g_bin_cnt[BINS];

__global__ void ghm_zero_kernel() {
    int i = threadIdx.x;
    if (i < BINS) {
        g_bin_nll[i] = 0.0;
        g_bin_cnt[i] = 0ULL;
    }
}

__global__ __launch_bounds__(256) void ghm_pass1_kernel(
    const float* __restrict__ x,
    const int* __restrict__ tgt,   // int32 (jax downgrades int64 without x64 mode)
    int N)
{
    // Thread-local per-bin accumulators (registers; bins indexed with
    // compile-time constants only, so no local-memory spill).
    float    lsum[BINS];
    unsigned lcnt[BINS];
#pragma unroll
    for (int b = 0; b < BINS; b++) { lsum[b] = 0.0f; lcnt[b] = 0u; }

    const int stride = gridDim.x * blockDim.x;
    for (int row = blockIdx.x * blockDim.x + threadIdx.x; row < N; row += stride) {
        const float4* p = reinterpret_cast<const float4*>(x + (size_t)row * C);
        float4 a  = p[0];
        float4 b4 = p[1];
        float4 c4 = p[2];
        float4 d4 = p[3];

        float v[C] = {a.x, a.y, a.z, a.w,
                      b4.x, b4.y, b4.z, b4.w,
                      c4.x, c4.y, c4.z, c4.w,
                      d4.x, d4.y, d4.z, d4.w};

        // row max
        float m = v[0];
#pragma unroll
        for (int i = 1; i < C; i++) m = fmaxf(m, v[i]);

        // sum of exp(x - m)
        float s = 0.0f;
#pragma unroll
        for (int i = 0; i < C; i++) s += expf(v[i] - m);

        int t = tgt[row];                 // expected in {0,1}
        t = min(max(t, 0), C - 1);        // crash-proof clamp (1 IMNMX)

        // dynamic-index element: scalar reload (L1 hit; avoids reg->local spill)
        float xt = __ldg(x + (size_t)row * C + t);

        float lse = m + logf(s);
        float nll = lse - xt;              // -log_softmax at target
        float pt  = expf(xt - lse);        // softmax prob at target
        float g   = fabsf(pt - (float)t);  // gradient norm

        // bin = searchsorted(arange(11)/10, g, side='right') - 1, clipped to 9
        int bin = 0;
#pragma unroll
        for (int j = 1; j <= BINS; j++) bin += (g >= (float)j / 10.0f) ? 1 : 0;
        if (bin > BINS - 1) bin = BINS - 1;

        lsum[bin] += nll;
        lcnt[bin] += 1u;
    }

    // ---- reduction: warp shuffle -> shared -> global double atomics ----
    __shared__ float    s_sum[BINS];
    __shared__ unsigned s_cnt[BINS];
    if (threadIdx.x < BINS) { s_sum[threadIdx.x] = 0.0f; s_cnt[threadIdx.x] = 0u; }
    __syncthreads();

#pragma unroll
    for (int b = 0; b < BINS; b++) {
        float    vs = lsum[b];
        unsigned vc = lcnt[b];
#pragma unroll
        for (int off = 16; off > 0; off >>= 1) {
            vs += __shfl_down_sync(0xFFFFFFFFu, vs, off);
            vc += __shfl_down_sync(0xFFFFFFFFu, vc, off);
        }
        if ((threadIdx.x & 31) == 0) {
            atomicAdd(&s_sum[b], vs);
            atomicAdd(&s_cnt[b], vc);
        }
    }
    __syncthreads();

    if (threadIdx.x < BINS) {
        atomicAdd(&g_bin_nll[threadIdx.x], (double)s_sum[threadIdx.x]);
        atomicAdd(&g_bin_cnt[threadIdx.x], (unsigned long long)s_cnt[threadIdx.x]);
    }
}

__global__ void ghm_finalize_kernel(float* out, int N) {
    if (threadIdx.x == 0 && blockIdx.x == 0) {
        double total = 0.0;
        double scale = (double)N / (double)BINS;
#pragma unroll
        for (int b = 0; b < BINS; b++) {
            double c = (double)g_bin_cnt[b];
            if (c < 1.0) c = 1.0;
            total += (scale / c) * g_bin_nll[b];
        }
        out[0] = (float)total;
    }
}

extern "C" void kernel_launch(void* const* d_in, const int* in_sizes, int n_in,
                              void* d_out, int out_size)
{
    // Robust input-order detection: inputs has C=16x more elements than target.
    int i_x = 0, i_t = 1;
    if (n_in >= 2 && in_sizes[1] > in_sizes[0]) { i_x = 1; i_t = 0; }

    const float* x   = (const float*)d_in[i_x];
    const int*   tgt = (const int*)d_in[i_t];
    float*       out = (float*)d_out;

    int N = in_sizes[i_t];             // number of rows (target count)
    (void)out_size;

    ghm_zero_kernel<<<1, 32>>>();

    const int threads = 256;
    int blocks = 2048;                 // grid-stride: ~8 rows/thread at N=4M
    int maxb = (N + threads - 1) / threads;
    if (blocks > maxb) blocks = maxb;

    ghm_pass1_kernel<<<blocks, threads>>>(x, tgt, N);
    ghm_finalize_kernel<<<1, 32>>>(out, N);
}